// round 4
// baseline (speedup 1.0000x reference)
#include <cuda_runtime.h>
#include <math.h>

#define TOK 1024
#define HID 2048
#define IMD 768
#define GUD (2*IMD)   // 1536
#define NE  8

typedef unsigned long long u64;

__device__ __forceinline__ float wsum(float v) {
#pragma unroll
    for (int o = 16; o; o >>= 1) v += __shfl_xor_sync(0xffffffffu, v, o);
    return v;
}

// One block per token. 256 threads = 8 warps.
// Computes router + top-2 + both expert FFNs + weighted combine, entirely
// within the block. No device-global scratch, no atomics, no inter-kernel deps.
// Every global access is guarded by the declared size of the buffer it touches.
__global__ __launch_bounds__(256, 1) void k_moe(
    const float* __restrict__ x,   const float* __restrict__ gw,
    const float* __restrict__ wgu, const float* __restrict__ wd,
    float* __restrict__ out,
    u64 sx, u64 sg, u64 sgu, u64 sd, u64 so)
{
    __shared__ __align__(16) float xs[HID];    // token activations
    __shared__ __align__(16) float hs[IMD];    // silu(g)*u
    __shared__ __align__(16) float acc[HID];   // output row accumulator
    __shared__ float lg[NE];

    const int t    = blockIdx.x;
    const int tid  = threadIdx.x;
    const int wid  = tid >> 5;
    const int lane = tid & 31;

    // ---- load x row ----
    const u64 xbase = (u64)t * HID;
    if (xbase + HID <= sx) {
        const float4* xr = (const float4*)(x + xbase);   // 8KB-stride rows: 16B aligned
        for (int j = tid; j < HID/4; j += 256) ((float4*)xs)[j] = xr[j];
    } else {
        for (int j = tid; j < HID; j += 256) xs[j] = (xbase + j < sx) ? x[xbase + j] : 0.f;
    }
    for (int n = tid; n < HID; n += 256) acc[n] = 0.f;
    __syncthreads();

    // ---- router: warp e computes logit e ----
    {
        const int e = wid;                               // 8 warps == 8 experts
        float s = 0.f;
        if ((u64)(e + 1) * HID <= sg) {
            const float* gr = gw + (size_t)e * HID;
            for (int j = lane; j < HID; j += 32) s += xs[j] * gr[j];
        }
        s = wsum(s);
        if (lane == 0) lg[e] = s;
    }
    __syncthreads();

    // ---- top-2 (redundantly by all threads; strict > keeps lowest index on ties) ----
    int i1 = 0; float v1 = lg[0];
#pragma unroll
    for (int e = 1; e < NE; e++) if (lg[e] > v1) { v1 = lg[e]; i1 = e; }
    int i2 = (i1 == 0) ? 1 : 0; float v2 = lg[i2];
#pragma unroll
    for (int e = 0; e < NE; e++) if (e != i1 && lg[e] > v2) { v2 = lg[e]; i2 = e; }
    // full-E softmax then top-2 renorm == 2-way softmax over {v1, v2}
    const float rr2 = expf(v2 - v1);          // <= 1
    const float w1  = 1.f / (1.f + rr2);
    const float w2  = rr2 * w1;

    const int   esel[2] = { i1, i2 };
    const float wsel[2] = { w1, w2 };

    // ---- two selected experts ----
    for (int s2 = 0; s2 < 2; s2++) {
        const int   e  = esel[s2];
        const float wt = wsel[s2];
        const u64 bgu = (u64)e * GUD * HID;
        const u64 bd  = (u64)e * HID * IMD;
        const bool okgu = (bgu + (u64)GUD * HID <= sgu);
        const bool okd  = (bd  + (u64)HID * IMD <= sd);

        __syncthreads();   // hs reused across s2 iterations

        // h[r] = silu(x . Wg[r]) * (x . Wu[r]);  warp handles rows r = wid mod 8
        for (int r = wid; r < IMD; r += 8) {
            float sg_ = 0.f, su_ = 0.f;
            if (okgu) {
                const float4* wg  = (const float4*)(wgu + bgu + (size_t)r * HID);
                const float4* wu  = (const float4*)(wgu + bgu + (size_t)(IMD + r) * HID);
                const float4* xv4 = (const float4*)xs;
#pragma unroll 4
                for (int j = lane; j < HID/4; j += 32) {   // 16 iters, uniform
                    float4 xv = xv4[j];
                    float4 a  = wg[j];
                    float4 b  = wu[j];
                    sg_ += xv.x*a.x + xv.y*a.y + xv.z*a.z + xv.w*a.w;
                    su_ += xv.x*b.x + xv.y*b.y + xv.z*b.z + xv.w*b.w;
                }
            }
            sg_ = wsum(sg_);
            su_ = wsum(su_);
            if (lane == 0) hs[r] = (sg_ / (1.f + expf(-sg_))) * su_;
        }
        __syncthreads();

        // acc[n] += wt * (h . Wd[n]);  warp handles cols n = wid mod 8
        for (int n = wid; n < HID; n += 8) {
            float s = 0.f;
            if (okd) {
                const float4* wr  = (const float4*)(wd + bd + (size_t)n * IMD);
                const float4* hv4 = (const float4*)hs;
#pragma unroll 4
                for (int i = lane; i < IMD/4; i += 32) {   // 6 iters, uniform
                    float4 h4 = hv4[i];
                    float4 c  = wr[i];
                    s += h4.x*c.x + h4.y*c.y + h4.z*c.z + h4.w*c.w;
                }
            }
            s = wsum(s);
            if (lane == 0) acc[n] += wt * s;
        }
    }
    __syncthreads();

    // ---- write output row (always written) ----
    const u64 ob = (u64)t * HID;
    for (int n = tid; n < HID; n += 256)
        if (ob + n < so) out[ob + n] = acc[n];
}

// ---------------- launch ----------------
extern "C" void kernel_launch(void* const* d_in, const int* in_sizes, int n_in,
                              void* d_out, int out_size) {
    const long EX = (long)TOK * HID;        // 2,097,152
    const long EG = (long)NE * HID;         //    16,384
    const long EU = (long)NE * GUD * HID;   // 25,165,824
    const long ED = (long)NE * HID * IMD;   // 12,582,912

    int ih = -1, ig = -1, iu = -1, id = -1;
    u64 sh = 0, sg = 0, su = 0, sd = 0;

    // Pass 1: element-count match
    for (int i = 0; i < n_in; i++) {
        long sz = in_sizes[i];
        if      (sz == EX && ih < 0) { ih = i; sh = (u64)EX; }
        else if (sz == EG && ig < 0) { ig = i; sg = (u64)EG; }
        else if (sz == EU && iu < 0) { iu = i; su = (u64)EU; }
        else if (sz == ED && id < 0) { id = i; sd = (u64)ED; }
    }
    // Pass 2: byte-count match
    if (ih < 0 || ig < 0 || iu < 0 || id < 0) {
        ih = ig = iu = id = -1;
        for (int i = 0; i < n_in; i++) {
            long sz = in_sizes[i];
            if      (sz == 4*EX && ih < 0) { ih = i; sh = (u64)EX; }
            else if (sz == 4*EG && ig < 0) { ig = i; sg = (u64)EG; }
            else if (sz == 4*EU && iu < 0) { iu = i; su = (u64)EU; }
            else if (sz == 4*ED && id < 0) { id = i; sd = (u64)ED; }
        }
    }
    // Pass 3: positional fallback (reference signature order), sizes as declared
    if ((ih < 0 || ig < 0 || iu < 0 || id < 0) && n_in >= 4) {
        ih = 0; sh = (u64)in_sizes[0];
        ig = 1; sg = (u64)in_sizes[1];
        iu = 2; su = (u64)in_sizes[2];
        id = 3; sd = (u64)in_sizes[3];
    }
    if (ih < 0 || ig < 0 || iu < 0 || id < 0) return;  // nothing sane to do

    const float* x   = (const float*)d_in[ih];
    const float* gw  = (const float*)d_in[ig];
    const float* wgu = (const float*)d_in[iu];
    const float* wd  = (const float*)d_in[id];
    float* out = (float*)d_out;

    k_moe<<<TOK, 256>>>(x, gw, wgu, wd, out, sh, sg, su, sd, (u64)out_size);
}

// round 5
// speedup vs baseline: 1.8941x; 1.8941x over previous
#include <cuda_runtime.h>
#include <math.h>

#define TOK 1024
#define HID 2048
#define IMD 768
#define GUD 1536
#define NE  8
#define NBLK 148

typedef unsigned long long u64;

// ---------------- scratch (device globals; zero-init at load) ----------------
__device__ __align__(16) int   g_cnt[NE];
__device__ __align__(16) int   g_list[NE*TOK];     // per-expert pair ids (pair = 2t+k)
__device__ __align__(16) float g_topw[2*TOK];      // renormalized top-2 weights
__device__ __align__(16) float g_gu [2*TOK*GUD];   // GEMM1 out (gate|up) per pair
__device__ __align__(16) float g_hb [2*TOK*IMD];   // silu(g)*u per pair
__device__ __align__(16) float g_o2 [2*TOK*HID];   // GEMM2 out per pair

// ---------------- grid-wide sense barrier (persistent kernel) ----------------
__device__ unsigned          g_bcnt   = 0;
__device__ volatile unsigned g_bsense = 0;

__device__ __forceinline__ void gbar(unsigned& ls) {
    __syncthreads();
    if (threadIdx.x == 0) {
        unsigned target = ls + 1u;
        __threadfence();
        unsigned old = atomicAdd(&g_bcnt, 1u);
        if (old == NBLK - 1u) {
            g_bcnt = 0u;
            __threadfence();
            g_bsense = target;
        } else {
            while (g_bsense != target) __nanosleep(128);
        }
        __threadfence();
    }
    ls += 1u;
    __syncthreads();
}

__device__ __forceinline__ float wsum(float v) {
#pragma unroll
    for (int o = 16; o; o >>= 1) v += __shfl_xor_sync(0xffffffffu, v, o);
    return v;
}

// ---------------- 128x128 register-blocked fp32 tile ----------------
// C[m,n] = sum_k A[row(m),k] * Bw[e][n0+n, k];  A rows gathered via g_list.
template<int KD, bool SECOND>
__device__ void gemm_tile(const float* __restrict__ A, const float* __restrict__ Be,
                          int e, int m0, int n0, int ne,
                          float (*As)[128], float (*Bs)[128]) {
    const int tid = threadIdx.x;
    const int tx = tid & 15, ty = tid >> 4;
    const int lr = tid >> 1, lk = (tid & 1) * 4;

    const float* a_ptr = nullptr;
    if (m0 + lr < ne) {
        int pair = g_list[e*TOK + m0 + lr];
        int arow = SECOND ? pair : (pair >> 1);
        a_ptr = A + (size_t)arow * KD;
    }
    const float* b_ptr = Be + (size_t)(n0 + lr) * KD;

    float acc[8][8];
#pragma unroll
    for (int i = 0; i < 8; i++)
#pragma unroll
        for (int j = 0; j < 8; j++) acc[i][j] = 0.f;

    float4 av = a_ptr ? *(const float4*)(a_ptr + lk) : make_float4(0,0,0,0);
    float4 bv = *(const float4*)(b_ptr + lk);

    for (int k0 = 0; k0 < KD; k0 += 8) {
        __syncthreads();
        As[lk+0][lr] = av.x; As[lk+1][lr] = av.y; As[lk+2][lr] = av.z; As[lk+3][lr] = av.w;
        Bs[lk+0][lr] = bv.x; Bs[lk+1][lr] = bv.y; Bs[lk+2][lr] = bv.z; Bs[lk+3][lr] = bv.w;
        __syncthreads();
        if (k0 + 8 < KD) {
            av = a_ptr ? *(const float4*)(a_ptr + k0 + 8 + lk) : make_float4(0,0,0,0);
            bv = *(const float4*)(b_ptr + k0 + 8 + lk);
        }
#pragma unroll
        for (int k = 0; k < 8; k++) {
            float4 a0 = *(const float4*)&As[k][ty*4];
            float4 a1 = *(const float4*)&As[k][64 + ty*4];
            float4 b0 = *(const float4*)&Bs[k][tx*4];
            float4 b1 = *(const float4*)&Bs[k][64 + tx*4];
            float a[8] = {a0.x,a0.y,a0.z,a0.w, a1.x,a1.y,a1.z,a1.w};
            float b[8] = {b0.x,b0.y,b0.z,b0.w, b1.x,b1.y,b1.z,b1.w};
#pragma unroll
            for (int i = 0; i < 8; i++)
#pragma unroll
                for (int j = 0; j < 8; j++)
                    acc[i][j] += a[i] * b[j];
        }
    }

#pragma unroll
    for (int mi = 0; mi < 8; mi++) {
        int r = m0 + (mi >> 2) * 64 + ty * 4 + (mi & 3);
        if (r >= ne) continue;
        int pair = g_list[e*TOK + r];
        float* crow = SECOND ? (g_o2 + (size_t)pair * HID + n0)
                             : (g_gu + (size_t)pair * GUD + n0);
#pragma unroll
        for (int cj = 0; cj < 2; cj++) {
            float4 v = make_float4(acc[mi][cj*4+0], acc[mi][cj*4+1],
                                   acc[mi][cj*4+2], acc[mi][cj*4+3]);
            *(float4*)(crow + cj*64 + tx*4) = v;
        }
    }
}

// ---------------- persistent fused MoE kernel ----------------
__global__ __launch_bounds__(256, 2) void k_moe(
    const float* __restrict__ x,   const float* __restrict__ gw,
    const float* __restrict__ wgu, const float* __restrict__ wd,
    float* __restrict__ out)
{
    __shared__ __align__(16) float As[8][128];
    __shared__ __align__(16) float Bs[8][128];

    const int tid  = threadIdx.x;
    const int wid  = tid >> 5;
    const int lane = tid & 31;
    const int bid  = blockIdx.x;
    unsigned ls = g_bsense;            // barrier sense snapshot (pre-run value)

    // ---- P0: zero expert counters ----
    if (bid == 0 && tid < NE) g_cnt[tid] = 0;
    gbar(ls);

    // ---- P1: router (one warp per token) ----
    {
        int t = bid * 8 + wid;         // 148*8 = 1184 >= 1024
        if (t < TOK) {
            const float* xr = x + (size_t)t * HID;
            float acc[NE];
#pragma unroll
            for (int e = 0; e < NE; e++) acc[e] = 0.f;
            for (int j = lane; j < HID; j += 32) {
                float xv = xr[j];
#pragma unroll
                for (int e = 0; e < NE; e++) acc[e] += xv * gw[e*HID + j];
            }
#pragma unroll
            for (int e = 0; e < NE; e++) acc[e] = wsum(acc[e]);
            if (lane == 0) {
                int i1 = 0; float v1 = acc[0];
#pragma unroll
                for (int e = 1; e < NE; e++) if (acc[e] > v1) { v1 = acc[e]; i1 = e; }
                int i2 = (i1 == 0) ? 1 : 0; float v2 = acc[i2];
#pragma unroll
                for (int e = 0; e < NE; e++) if (e != i1 && acc[e] > v2) { v2 = acc[e]; i2 = e; }
                float r  = expf(v2 - v1);          // full-E softmax + top-2 renorm
                float w1 = 1.f / (1.f + r);        // == 2-way softmax over {v1,v2}
                g_topw[2*t+0] = w1;
                g_topw[2*t+1] = r * w1;
                int p1 = atomicAdd(&g_cnt[i1], 1); g_list[i1*TOK + p1] = 2*t + 0;
                int p2 = atomicAdd(&g_cnt[i2], 1); g_list[i2*TOK + p2] = 2*t + 1;
            }
        }
    }
    gbar(ls);

    // ---- P2: GEMM1 (gathered x @ Wgu^T), jobs: e * mt(8) * nt(12) ----
    for (int job = bid; job < NE*8*12; job += NBLK) {
        int e  = job / 96;
        int mt = (job % 96) / 12;
        int nt = job % 12;
        int ne = g_cnt[e];
        if (mt * 128 >= ne) continue;
        gemm_tile<HID, false>(x, wgu + (size_t)e*GUD*HID, e, mt*128, nt*128, ne, As, Bs);
    }
    gbar(ls);

    // ---- P3: activation h = silu(g)*u ----
    {
        const int n4 = 2*TOK*IMD/4;            // 393216 float4s
        for (int i = bid*256 + tid; i < n4; i += NBLK*256) {
            int p  = i / (IMD/4);
            int j4 = i - p * (IMD/4);
            float4 g4 = *(const float4*)(g_gu + (size_t)p*GUD + 4*j4);
            float4 u4 = *(const float4*)(g_gu + (size_t)p*GUD + IMD + 4*j4);
            float4 h4;
            h4.x = (g4.x / (1.f + expf(-g4.x))) * u4.x;
            h4.y = (g4.y / (1.f + expf(-g4.y))) * u4.y;
            h4.z = (g4.z / (1.f + expf(-g4.z))) * u4.z;
            h4.w = (g4.w / (1.f + expf(-g4.w))) * u4.w;
            *(float4*)(g_hb + (size_t)p*IMD + 4*j4) = h4;
        }
    }
    gbar(ls);

    // ---- P4: GEMM2 (gathered h @ Wd^T), jobs: e * mt(8) * nt(16) ----
    for (int job = bid; job < NE*8*16; job += NBLK) {
        int e  = job / 128;
        int mt = (job % 128) / 16;
        int nt = job % 16;
        int ne = g_cnt[e];
        if (mt * 128 >= ne) continue;
        gemm_tile<IMD, true>(g_hb, wd + (size_t)e*HID*IMD, e, mt*128, nt*128, ne, As, Bs);
    }
    gbar(ls);

    // ---- P5: combine out[t] = w1*y[2t] + w2*y[2t+1] ----
    {
        const int n4 = TOK*HID/4;
        for (int i = bid*256 + tid; i < n4; i += NBLK*256) {
            int t  = i / (HID/4);
            int j4 = i - t * (HID/4);
            float w1 = g_topw[2*t+0], w2 = g_topw[2*t+1];
            float4 y1 = ((const float4*)g_o2)[(size_t)(2*t  )*(HID/4) + j4];
            float4 y2 = ((const float4*)g_o2)[(size_t)(2*t+1)*(HID/4) + j4];
            float4 o;
            o.x = w1*y1.x + w2*y2.x;
            o.y = w1*y1.y + w2*y2.y;
            o.z = w1*y1.z + w2*y2.z;
            o.w = w1*y1.w + w2*y2.w;
            ((float4*)out)[i] = o;
        }
    }
}

// ---------------- launch ----------------
extern "C" void kernel_launch(void* const* d_in, const int* in_sizes, int n_in,
                              void* d_out, int out_size) {
    const long EX = (long)TOK*HID, EG = (long)NE*HID;
    const long EU = (long)NE*GUD*HID, ED = (long)NE*HID*IMD;

    const float *x = nullptr, *gw = nullptr, *wgu = nullptr, *wd = nullptr;
    for (int i = 0; i < n_in; i++) {
        long sz = in_sizes[i];
        if      (sz == EX && !x)   x   = (const float*)d_in[i];
        else if (sz == EG && !gw)  gw  = (const float*)d_in[i];
        else if (sz == EU && !wgu) wgu = (const float*)d_in[i];
        else if (sz == ED && !wd)  wd  = (const float*)d_in[i];
    }
    if (!x || !gw || !wgu || !wd) {   // positional fallback (signature order)
        if (n_in < 4) return;
        x = (const float*)d_in[0]; gw = (const float*)d_in[1];
        wgu = (const float*)d_in[2]; wd = (const float*)d_in[3];
    }
    k_moe<<<NBLK, 256>>>(x, gw, wgu, wd, (float*)d_out);
}

// round 7
// speedup vs baseline: 4.3184x; 2.2799x over previous
#include <cuda_runtime.h>
#include <cuda_bf16.h>
#include <math.h>
#include <stdint.h>

#define TOK 1024
#define HID 2048
#define IMD 768
#define GUD 1536
#define NE  8
#define NBLK 148
#define NT (NBLK*256)

// ---- smem byte offsets: 4 matrices of 128 rows x 64 bf16 (128B swizzled rows) ----
#define SA_H 0
#define SA_L 16384
#define SB_H 32768
#define SB_L 49152
#define SMEM_BYTES 65536

// ---------------- scratch (device globals) ----------------
__device__ __align__(16) int   g_cnt[NE];
__device__ __align__(16) int   g_list[NE*TOK];
__device__ __align__(16) float g_topw[2*TOK];
__device__ __align__(16) float g_gu[2*TOK*GUD];     // GEMM1 out fp32
__device__ __align__(16) float g_o2[2*TOK*HID];     // GEMM2 out fp32
__device__ __align__(16) __nv_bfloat16 g_xh [TOK*HID],     g_xl [TOK*HID];
__device__ __align__(16) __nv_bfloat16 g_wuh[NE*GUD*HID],  g_wul[NE*GUD*HID];
__device__ __align__(16) __nv_bfloat16 g_wdh[NE*HID*IMD],  g_wdl[NE*HID*IMD];
__device__ __align__(16) __nv_bfloat16 g_hbh[2*TOK*IMD],   g_hbl[2*TOK*IMD];
__device__ unsigned          g_bcnt   = 0;
__device__ volatile unsigned g_bsense = 0;

// ---------------- helpers ----------------
__device__ __forceinline__ uint32_t smem_u32(const void* p) {
    uint32_t a;
    asm("{ .reg .u64 t; cvta.to.shared.u64 t, %1; cvt.u32.u64 %0, t; }" : "=r"(a) : "l"(p));
    return a;
}
__device__ __forceinline__ void ldsm_x4(uint32_t r[4], uint32_t addr) {
    asm volatile("ldmatrix.sync.aligned.m8n8.x4.shared.b16 {%0,%1,%2,%3}, [%4];"
        : "=r"(r[0]), "=r"(r[1]), "=r"(r[2]), "=r"(r[3]) : "r"(addr));
}
__device__ __forceinline__ void mma_bf16(float c[4], const uint32_t a[4], const uint32_t b[2]) {
    asm volatile("mma.sync.aligned.m16n8k16.row.col.f32.bf16.bf16.f32 "
        "{%0,%1,%2,%3}, {%4,%5,%6,%7}, {%8,%9}, {%0,%1,%2,%3};"
        : "+f"(c[0]), "+f"(c[1]), "+f"(c[2]), "+f"(c[3])
        : "r"(a[0]), "r"(a[1]), "r"(a[2]), "r"(a[3]), "r"(b[0]), "r"(b[1]));
}
__device__ __forceinline__ void split4(float4 v, uint2& hi, uint2& lo) {
    __nv_bfloat16 h0 = __float2bfloat16(v.x), h1 = __float2bfloat16(v.y);
    __nv_bfloat16 h2 = __float2bfloat16(v.z), h3 = __float2bfloat16(v.w);
    __nv_bfloat16 l0 = __float2bfloat16(v.x - __bfloat162float(h0));
    __nv_bfloat16 l1 = __float2bfloat16(v.y - __bfloat162float(h1));
    __nv_bfloat16 l2 = __float2bfloat16(v.z - __bfloat162float(h2));
    __nv_bfloat16 l3 = __float2bfloat16(v.w - __bfloat162float(h3));
    hi.x = (uint32_t)__bfloat16_as_ushort(h0) | ((uint32_t)__bfloat16_as_ushort(h1) << 16);
    hi.y = (uint32_t)__bfloat16_as_ushort(h2) | ((uint32_t)__bfloat16_as_ushort(h3) << 16);
    lo.x = (uint32_t)__bfloat16_as_ushort(l0) | ((uint32_t)__bfloat16_as_ushort(l1) << 16);
    lo.y = (uint32_t)__bfloat16_as_ushort(l2) | ((uint32_t)__bfloat16_as_ushort(l3) << 16);
}
__device__ __forceinline__ void gbar(unsigned& ls) {
    __syncthreads();
    if (threadIdx.x == 0) {
        unsigned target = ls + 1u;
        __threadfence();
        unsigned old = atomicAdd(&g_bcnt, 1u);
        if (old == NBLK - 1u) { g_bcnt = 0u; __threadfence(); g_bsense = target; }
        else { while (g_bsense != target) __nanosleep(128); }
        __threadfence();
    }
    ls += 1u;
    __syncthreads();
}
__device__ __forceinline__ float wsum(float v) {
#pragma unroll
    for (int o = 16; o; o >>= 1) v += __shfl_xor_sync(0xffffffffu, v, o);
    return v;
}

// ---------------- 128x128x(K) warp-MMA tile, gathered A rows ----------------
// C[m,n] = sum_k A[row(m),k]*B[n,k], A/B given as bf16 hi/lo pairs.
template<int KD, bool SECOND>
__device__ __forceinline__ void mma_tile(
    const __nv_bfloat16* __restrict__ Ah, const __nv_bfloat16* __restrict__ Al,
    const __nv_bfloat16* __restrict__ Bh, const __nv_bfloat16* __restrict__ Bl,
    int e, int m0, int n0, int ne, char* sm, uint32_t sb)
{
    const int tid = threadIdx.x;
    const int wid = tid >> 5, lane = tid & 31;

    // ---- global->smem load mapping: thread = (row, 4 chunks of 16B) ----
    const int lrow = tid >> 1;
    const int cq   = (tid & 1) * 4;
    const uint4* agh = nullptr; const uint4* agl = nullptr;
    if (m0 + lrow < ne) {
        int pair = g_list[e*TOK + m0 + lrow];
        size_t ar = (size_t)(SECOND ? pair : (pair >> 1)) * KD;
        agh = (const uint4*)(Ah + ar);
        agl = (const uint4*)(Al + ar);
    }
    const uint4* bgh = (const uint4*)(Bh + (size_t)(n0 + lrow) * KD);
    const uint4* bgl = (const uint4*)(Bl + (size_t)(n0 + lrow) * KD);

    uint32_t sts[4];
#pragma unroll
    for (int j = 0; j < 4; j++) {
        int ch = cq + j;
        sts[j] = (uint32_t)(lrow * 128 + ((ch ^ (lrow & 7)) << 4));
    }

    // ---- warp tile: 32m x 64n ----
    const int wm = (wid & 3) * 32;
    const int wn = (wid >> 2) * 64;
    const int q  = lane >> 3, r8 = lane & 7;
    const int a_m_base = wm + (q & 1) * 8 + r8;   // + mi*16
    const int a_ch_off = (q >> 1);                 // + ks*2
    const int b_n_base = wn + (q >> 1) * 8 + r8;   // + nb*16
    const int b_ch_off = (q & 1);                  // + ks*2
    const uint32_t saH = sb + SA_H, saL = sb + SA_L;
    const uint32_t sbH = sb + SB_H, sbL = sb + SB_L;

    float acc[2][8][4];
#pragma unroll
    for (int i = 0; i < 2; i++)
#pragma unroll
        for (int j = 0; j < 8; j++)
#pragma unroll
            for (int c = 0; c < 4; c++) acc[i][j][c] = 0.f;

    for (int kb = 0; kb < KD / 64; kb++) {
        __syncthreads();
#pragma unroll
        for (int j = 0; j < 4; j++) {
            int ch = cq + j;
            uint4 z = make_uint4(0,0,0,0);
            *(uint4*)(sm + SA_H + sts[j]) = agh ? agh[kb*8 + ch] : z;
            *(uint4*)(sm + SA_L + sts[j]) = agl ? agl[kb*8 + ch] : z;
            *(uint4*)(sm + SB_H + sts[j]) = bgh[kb*8 + ch];
            *(uint4*)(sm + SB_L + sts[j]) = bgl[kb*8 + ch];
        }
        __syncthreads();

#pragma unroll
        for (int ks = 0; ks < 4; ks++) {
            uint32_t ahf[2][4], alf[2][4];
#pragma unroll
            for (int mi = 0; mi < 2; mi++) {
                int m_ld = a_m_base + mi * 16;
                uint32_t off = (uint32_t)(m_ld * 128 + (((ks*2 + a_ch_off) ^ (m_ld & 7)) << 4));
                ldsm_x4(ahf[mi], saH + off);
                ldsm_x4(alf[mi], saL + off);
            }
#pragma unroll
            for (int nb = 0; nb < 4; nb++) {
                int n_ld = b_n_base + nb * 16;
                uint32_t off = (uint32_t)(n_ld * 128 + (((ks*2 + b_ch_off) ^ (n_ld & 7)) << 4));
                uint32_t bhf[4], blf[4];
                ldsm_x4(bhf, sbH + off);
                ldsm_x4(blf, sbL + off);
#pragma unroll
                for (int mi = 0; mi < 2; mi++) {
#pragma unroll
                    for (int h = 0; h < 2; h++) {
                        float* c = acc[mi][nb*2 + h];
                        mma_bf16(c, ahf[mi], &bhf[2*h]);
                        mma_bf16(c, ahf[mi], &blf[2*h]);
                        mma_bf16(c, alf[mi], &bhf[2*h]);
                    }
                }
            }
        }
    }

    // ---- epilogue: c0,c1 -> (m=g, n=2t,2t+1); c2,c3 -> (m=g+8) ----
    const int g  = lane >> 2, t4 = lane & 3;
#pragma unroll
    for (int mi = 0; mi < 2; mi++) {
        int mr0 = m0 + wm + mi*16 + g;
        int mr1 = mr0 + 8;
        float* row0 = nullptr; float* row1 = nullptr;
        if (mr0 < ne) {
            int p = g_list[e*TOK + mr0];
            row0 = SECOND ? (g_o2 + (size_t)p * HID) : (g_gu + (size_t)p * GUD);
        }
        if (mr1 < ne) {
            int p = g_list[e*TOK + mr1];
            row1 = SECOND ? (g_o2 + (size_t)p * HID) : (g_gu + (size_t)p * GUD);
        }
#pragma unroll
        for (int nj = 0; nj < 8; nj++) {
            int n = n0 + wn + nj*8 + t4*2;
            if (row0) *(float2*)(row0 + n) = make_float2(acc[mi][nj][0], acc[mi][nj][1]);
            if (row1) *(float2*)(row1 + n) = make_float2(acc[mi][nj][2], acc[mi][nj][3]);
        }
    }
    __syncthreads();
}

// ---------------- persistent fused MoE kernel ----------------
__global__ void __launch_bounds__(256) k_moe(
    const float* __restrict__ x,   const float* __restrict__ gw,
    const float* __restrict__ wgu, const float* __restrict__ wd,
    float* __restrict__ out)
{
    extern __shared__ char sm[];
    const uint32_t sb = smem_u32(sm);
    const int tid  = threadIdx.x;
    const int wid  = tid >> 5;
    const int lane = tid & 31;
    const int bid  = blockIdx.x;
    const int gtid = bid * 256 + tid;
    unsigned ls = g_bsense;

    // ---- P0: zero counters + split inputs/weights to bf16 hi/lo ----
    if (bid == 0 && tid < NE) g_cnt[tid] = 0;
    {
        uint2 hi, lo;
        for (long i = gtid; i < (long)TOK*HID/4; i += NT) {
            split4(((const float4*)x)[i], hi, lo);
            ((uint2*)g_xh)[i] = hi; ((uint2*)g_xl)[i] = lo;
        }
        for (long i = gtid; i < (long)NE*GUD*HID/4; i += NT) {
            split4(((const float4*)wgu)[i], hi, lo);
            ((uint2*)g_wuh)[i] = hi; ((uint2*)g_wul)[i] = lo;
        }
        for (long i = gtid; i < (long)NE*HID*IMD/4; i += NT) {
            split4(((const float4*)wd)[i], hi, lo);
            ((uint2*)g_wdh)[i] = hi; ((uint2*)g_wdl)[i] = lo;
        }
    }
    gbar(ls);

    // ---- P1: router (one warp per token) ----
    {
        int t = bid * 8 + wid;
        if (t < TOK) {
            const float* xr = x + (size_t)t * HID;
            float acc[NE];
#pragma unroll
            for (int e2 = 0; e2 < NE; e2++) acc[e2] = 0.f;
            for (int j = lane; j < HID; j += 32) {
                float xv = xr[j];
#pragma unroll
                for (int e2 = 0; e2 < NE; e2++) acc[e2] += xv * gw[e2*HID + j];
            }
#pragma unroll
            for (int e2 = 0; e2 < NE; e2++) acc[e2] = wsum(acc[e2]);
            if (lane == 0) {
                int i1 = 0; float v1 = acc[0];
#pragma unroll
                for (int e2 = 1; e2 < NE; e2++) if (acc[e2] > v1) { v1 = acc[e2]; i1 = e2; }
                int i2 = (i1 == 0) ? 1 : 0; float v2 = acc[i2];
#pragma unroll
                for (int e2 = 0; e2 < NE; e2++) if (e2 != i1 && acc[e2] > v2) { v2 = acc[e2]; i2 = e2; }
                float r  = expf(v2 - v1);          // full-E softmax + top-2 renorm
                float w1 = 1.f / (1.f + r);        // == 2-way softmax over {v1,v2}
                g_topw[2*t+0] = w1;
                g_topw[2*t+1] = r * w1;
                int p1 = atomicAdd(&g_cnt[i1], 1); g_list[i1*TOK + p1] = 2*t + 0;
                int p2 = atomicAdd(&g_cnt[i2], 1); g_list[i2*TOK + p2] = 2*t + 1;
            }
        }
    }
    gbar(ls);

    // ---- P2: GEMM1  x @ Wgu^T -> g_gu  (K=2048, N=1536) ----
    for (int job = bid; job < NE*8*12; job += NBLK) {
        int e  = job / 96;
        int mt = (job % 96) / 12;
        int nt = job % 12;
        int ne = g_cnt[e];
        if (mt * 128 >= ne) continue;
        mma_tile<HID, false>(g_xh, g_xl,
                             g_wuh + (size_t)e*GUD*HID, g_wul + (size_t)e*GUD*HID,
                             e, mt*128, nt*128, ne, sm, sb);
    }
    gbar(ls);

    // ---- P3: act h = silu(g)*u -> bf16 hi/lo ----
    {
        const int n4 = 2*TOK*IMD/4;
        for (int i = gtid; i < n4; i += NT) {
            int p  = i / (IMD/4);
            int j4 = i - p * (IMD/4);
            float4 g4 = *(const float4*)(g_gu + (size_t)p*GUD + 4*j4);
            float4 u4 = *(const float4*)(g_gu + (size_t)p*GUD + IMD + 4*j4);
            float4 h4;
            h4.x = (g4.x / (1.f + expf(-g4.x))) * u4.x;
            h4.y = (g4.y / (1.f + expf(-g4.y))) * u4.y;
            h4.z = (g4.z / (1.f + expf(-g4.z))) * u4.z;
            h4.w = (g4.w / (1.f + expf(-g4.w))) * u4.w;
            uint2 hi, lo;
            split4(h4, hi, lo);
            ((uint2*)g_hbh)[i] = hi; ((uint2*)g_hbl)[i] = lo;
        }
    }
    gbar(ls);

    // ---- P4: GEMM2  h @ Wd^T -> g_o2  (K=768, N=2048) ----
    for (int job = bid; job < NE*8*16; job += NBLK) {
        int e  = job / 128;
        int mt = (job % 128) / 16;
        int nt = job % 16;
        int ne = g_cnt[e];
        if (mt * 128 >= ne) continue;
        mma_tile<IMD, true>(g_hbh, g_hbl,
                            g_wdh + (size_t)e*HID*IMD, g_wdl + (size_t)e*HID*IMD,
                            e, mt*128, nt*128, ne, sm, sb);
    }
    gbar(ls);

    // ---- P5: combine out[t] = w1*y[2t] + w2*y[2t+1] ----
    {
        const int n4 = TOK*HID/4;
        for (int i = gtid; i < n4; i += NT) {
            int t  = i / (HID/4);
            int j4 = i - t * (HID/4);
            float w1 = g_topw[2*t+0], w2 = g_topw[2*t+1];
            float4 y1 = ((const float4*)g_o2)[(size_t)(2*t  )*(HID/4) + j4];
            float4 y2 = ((const float4*)g_o2)[(size_t)(2*t+1)*(HID/4) + j4];
            float4 o;
            o.x = w1*y1.x + w2*y2.x;
            o.y = w1*y1.y + w2*y2.y;
            o.z = w1*y1.z + w2*y2.z;
            o.w = w1*y1.w + w2*y2.w;
            ((float4*)out)[i] = o;
        }
    }
}

// ---------------- launch ----------------
extern "C" void kernel_launch(void* const* d_in, const int* in_sizes, int n_in,
                              void* d_out, int out_size) {
    const long EX = (long)TOK*HID, EG = (long)NE*HID;
    const long EU = (long)NE*GUD*HID, ED = (long)NE*HID*IMD;

    const float *x = nullptr, *gw = nullptr, *wgu = nullptr, *wd = nullptr;
    for (int i = 0; i < n_in; i++) {
        long sz = in_sizes[i];
        if      (sz == EX && !x)   x   = (const float*)d_in[i];
        else if (sz == EG && !gw)  gw  = (const float*)d_in[i];
        else if (sz == EU && !wgu) wgu = (const float*)d_in[i];
        else if (sz == ED && !wd)  wd  = (const float*)d_in[i];
    }
    if (!x || !gw || !wgu || !wd) {
        if (n_in < 4) return;
        x = (const float*)d_in[0]; gw = (const float*)d_in[1];
        wgu = (const float*)d_in[2]; wd = (const float*)d_in[3];
    }
    cudaFuncSetAttribute(k_moe, cudaFuncAttributeMaxDynamicSharedMemorySize, SMEM_BYTES);
    k_moe<<<NBLK, 256, SMEM_BYTES>>>(x, gw, wgu, wd, (float*)d_out);
}

// round 8
// speedup vs baseline: 5.1132x; 1.1841x over previous
#include <cuda_runtime.h>
#include <cuda_bf16.h>
#include <math.h>
#include <stdint.h>

#define TOK 1024
#define HID 2048
#define IMD 768
#define GUD 1536
#define NE  8
#define NBLK 148
#define NT (NBLK*256)

// ---- per-stage smem layout: 4 matrices of 128 rows x 64 bf16 (swizzled 128B rows) ----
#define SA_H 0
#define SA_L 16384
#define SB_H 32768
#define SB_L 49152
#define STAGE_BYTES 65536
#define SMEM_BYTES (2*STAGE_BYTES)

// ---------------- scratch (device globals) ----------------
__device__ __align__(16) int   g_cnt[NE];
__device__ __align__(16) int   g_list[NE*TOK];
__device__ __align__(16) float g_topw[2*TOK];
__device__ __align__(16) float g_gu[2*TOK*GUD];     // GEMM1 out fp32
__device__ __align__(16) float g_o2[2*TOK*HID];     // GEMM2 out fp32
__device__ __align__(16) __nv_bfloat16 g_xh [TOK*HID],     g_xl [TOK*HID];
__device__ __align__(16) __nv_bfloat16 g_wuh[NE*GUD*HID],  g_wul[NE*GUD*HID];
__device__ __align__(16) __nv_bfloat16 g_wdh[NE*HID*IMD],  g_wdl[NE*HID*IMD];
__device__ __align__(16) __nv_bfloat16 g_hbh[2*TOK*IMD],   g_hbl[2*TOK*IMD];
__device__ unsigned          g_bcnt   = 0;
__device__ volatile unsigned g_bsense = 0;

// ---------------- helpers ----------------
__device__ __forceinline__ uint32_t smem_u32(const void* p) {
    uint32_t a;
    asm("{ .reg .u64 t; cvta.to.shared.u64 t, %1; cvt.u32.u64 %0, t; }" : "=r"(a) : "l"(p));
    return a;
}
__device__ __forceinline__ void cp16(uint32_t dst, const void* src) {
    asm volatile("cp.async.cg.shared.global [%0], [%1], 16;" :: "r"(dst), "l"(src) : "memory");
}
// src_size=0 -> zero-fill (no global read of consequence)
__device__ __forceinline__ void cp16p(uint32_t dst, const void* src, int full) {
    asm volatile("cp.async.cg.shared.global [%0], [%1], 16, %2;"
                 :: "r"(dst), "l"(src), "r"(full ? 16 : 0) : "memory");
}
#define CP_COMMIT() asm volatile("cp.async.commit_group;" ::: "memory")
#define CP_WAIT(n)  asm volatile("cp.async.wait_group %0;" :: "n"(n) : "memory")

__device__ __forceinline__ void ldsm_x4(uint32_t r[4], uint32_t addr) {
    asm volatile("ldmatrix.sync.aligned.m8n8.x4.shared.b16 {%0,%1,%2,%3}, [%4];"
        : "=r"(r[0]), "=r"(r[1]), "=r"(r[2]), "=r"(r[3]) : "r"(addr));
}
__device__ __forceinline__ void mma_bf16(float c[4], const uint32_t a[4], const uint32_t b[2]) {
    asm volatile("mma.sync.aligned.m16n8k16.row.col.f32.bf16.bf16.f32 "
        "{%0,%1,%2,%3}, {%4,%5,%6,%7}, {%8,%9}, {%0,%1,%2,%3};"
        : "+f"(c[0]), "+f"(c[1]), "+f"(c[2]), "+f"(c[3])
        : "r"(a[0]), "r"(a[1]), "r"(a[2]), "r"(a[3]), "r"(b[0]), "r"(b[1]));
}
__device__ __forceinline__ void split4(float4 v, uint2& hi, uint2& lo) {
    __nv_bfloat16 h0 = __float2bfloat16(v.x), h1 = __float2bfloat16(v.y);
    __nv_bfloat16 h2 = __float2bfloat16(v.z), h3 = __float2bfloat16(v.w);
    __nv_bfloat16 l0 = __float2bfloat16(v.x - __bfloat162float(h0));
    __nv_bfloat16 l1 = __float2bfloat16(v.y - __bfloat162float(h1));
    __nv_bfloat16 l2 = __float2bfloat16(v.z - __bfloat162float(h2));
    __nv_bfloat16 l3 = __float2bfloat16(v.w - __bfloat162float(h3));
    hi.x = (uint32_t)__bfloat16_as_ushort(h0) | ((uint32_t)__bfloat16_as_ushort(h1) << 16);
    hi.y = (uint32_t)__bfloat16_as_ushort(h2) | ((uint32_t)__bfloat16_as_ushort(h3) << 16);
    lo.x = (uint32_t)__bfloat16_as_ushort(l0) | ((uint32_t)__bfloat16_as_ushort(l1) << 16);
    lo.y = (uint32_t)__bfloat16_as_ushort(l2) | ((uint32_t)__bfloat16_as_ushort(l3) << 16);
}
__device__ __forceinline__ void gbar(unsigned& ls) {
    __syncthreads();
    if (threadIdx.x == 0) {
        unsigned target = ls + 1u;
        __threadfence();
        unsigned old = atomicAdd(&g_bcnt, 1u);
        if (old == NBLK - 1u) { g_bcnt = 0u; __threadfence(); g_bsense = target; }
        else { while (g_bsense != target) __nanosleep(128); }
        __threadfence();
    }
    ls += 1u;
    __syncthreads();
}
__device__ __forceinline__ float wsum(float v) {
#pragma unroll
    for (int o = 16; o; o >>= 1) v += __shfl_xor_sync(0xffffffffu, v, o);
    return v;
}

// ---------------- 128x128x(K) warp-MMA tile, gathered A rows, 2-stage cp.async ----
template<int KD, bool SECOND>
__device__ __forceinline__ void mma_tile(
    const __nv_bfloat16* __restrict__ Ah, const __nv_bfloat16* __restrict__ Al,
    const __nv_bfloat16* __restrict__ Bh, const __nv_bfloat16* __restrict__ Bl,
    int e, int m0, int n0, int ne, char* sm, uint32_t sb)
{
    const int tid = threadIdx.x;
    const int wid = tid >> 5, lane = tid & 31;

    // ---- global->smem mapping: thread = (row, 4 chunks of 16B per matrix) ----
    const int lrow = tid >> 1;
    const int cq   = (tid & 1) * 4;
    const int a_ok = (m0 + lrow < ne);
    const uint4 *agh, *agl;
    {
        int pair = a_ok ? g_list[e*TOK + m0 + lrow] : 0;
        size_t ar = (size_t)(SECOND ? pair : (pair >> 1)) * KD;
        agh = (const uint4*)(Ah + ar);
        agl = (const uint4*)(Al + ar);
    }
    const uint4* bgh = (const uint4*)(Bh + (size_t)(n0 + lrow) * KD);
    const uint4* bgl = (const uint4*)(Bl + (size_t)(n0 + lrow) * KD);

    uint32_t sts[4];
#pragma unroll
    for (int j = 0; j < 4; j++) {
        int ch = cq + j;
        sts[j] = (uint32_t)(lrow * 128 + ((ch ^ (lrow & 7)) << 4));
    }

    const int KBN = KD / 64;
    auto issue = [&](int kb, int stg) {
        uint32_t base = sb + (uint32_t)stg * STAGE_BYTES;
#pragma unroll
        for (int j = 0; j < 4; j++) {
            int ch = cq + j;
            cp16p(base + SA_H + sts[j], agh + kb*8 + ch, a_ok);
            cp16p(base + SA_L + sts[j], agl + kb*8 + ch, a_ok);
            cp16 (base + SB_H + sts[j], bgh + kb*8 + ch);
            cp16 (base + SB_L + sts[j], bgl + kb*8 + ch);
        }
        CP_COMMIT();
    };

    // ---- warp tile: 32m x 64n ----
    const int wm = (wid & 3) * 32;
    const int wn = (wid >> 2) * 64;
    const int q  = lane >> 3, r8 = lane & 7;
    const int a_m_base = wm + (q & 1) * 8 + r8;
    const int a_ch_off = (q >> 1);
    const int b_n_base = wn + (q >> 1) * 8 + r8;
    const int b_ch_off = (q & 1);

    float acc[2][8][4];
#pragma unroll
    for (int i = 0; i < 2; i++)
#pragma unroll
        for (int j = 0; j < 8; j++)
#pragma unroll
            for (int c = 0; c < 4; c++) acc[i][j][c] = 0.f;

    issue(0, 0);

    for (int kb = 0; kb < KBN; kb++) {
        const int stg = kb & 1;
        if (kb + 1 < KBN) issue(kb + 1, stg ^ 1);
        if (kb + 1 < KBN) { CP_WAIT(1); } else { CP_WAIT(0); }
        __syncthreads();

        const uint32_t base = sb + (uint32_t)stg * STAGE_BYTES;
        const uint32_t saH = base + SA_H, saL = base + SA_L;
        const uint32_t sbH = base + SB_H, sbL = base + SB_L;

#pragma unroll
        for (int ks = 0; ks < 4; ks++) {
            uint32_t ahf[2][4], alf[2][4];
#pragma unroll
            for (int mi = 0; mi < 2; mi++) {
                int m_ld = a_m_base + mi * 16;
                uint32_t off = (uint32_t)(m_ld * 128 + (((ks*2 + a_ch_off) ^ (m_ld & 7)) << 4));
                ldsm_x4(ahf[mi], saH + off);
                ldsm_x4(alf[mi], saL + off);
            }
#pragma unroll
            for (int nb = 0; nb < 4; nb++) {
                int n_ld = b_n_base + nb * 16;
                uint32_t off = (uint32_t)(n_ld * 128 + (((ks*2 + b_ch_off) ^ (n_ld & 7)) << 4));
                uint32_t bhf[4], blf[4];
                ldsm_x4(bhf, sbH + off);
                ldsm_x4(blf, sbL + off);
#pragma unroll
                for (int mi = 0; mi < 2; mi++) {
#pragma unroll
                    for (int h = 0; h < 2; h++) {
                        float* c = acc[mi][nb*2 + h];
                        mma_bf16(c, ahf[mi], &bhf[2*h]);
                        mma_bf16(c, ahf[mi], &blf[2*h]);
                        mma_bf16(c, alf[mi], &bhf[2*h]);
                    }
                }
            }
        }
        __syncthreads();   // all warps done reading stage stg before it is refilled
    }

    // ---- epilogue ----
    const int g  = lane >> 2, t4 = lane & 3;
#pragma unroll
    for (int mi = 0; mi < 2; mi++) {
        int mr0 = m0 + wm + mi*16 + g;
        int mr1 = mr0 + 8;
        float* row0 = nullptr; float* row1 = nullptr;
        if (mr0 < ne) {
            int p = g_list[e*TOK + mr0];
            row0 = SECOND ? (g_o2 + (size_t)p * HID) : (g_gu + (size_t)p * GUD);
        }
        if (mr1 < ne) {
            int p = g_list[e*TOK + mr1];
            row1 = SECOND ? (g_o2 + (size_t)p * HID) : (g_gu + (size_t)p * GUD);
        }
#pragma unroll
        for (int nj = 0; nj < 8; nj++) {
            int n = n0 + wn + nj*8 + t4*2;
            if (row0) *(float2*)(row0 + n) = make_float2(acc[mi][nj][0], acc[mi][nj][1]);
            if (row1) *(float2*)(row1 + n) = make_float2(acc[mi][nj][2], acc[mi][nj][3]);
        }
    }
    __syncthreads();
}

// ---------------- persistent fused MoE kernel ----------------
__global__ void __launch_bounds__(256) k_moe(
    const float* __restrict__ x,   const float* __restrict__ gw,
    const float* __restrict__ wgu, const float* __restrict__ wd,
    float* __restrict__ out)
{
    extern __shared__ char sm[];
    const uint32_t sb = smem_u32(sm);
    const int tid  = threadIdx.x;
    const int wid  = tid >> 5;
    const int lane = tid & 31;
    const int bid  = blockIdx.x;
    const int gtid = bid * 256 + tid;
    unsigned ls = g_bsense;

    // ---- P0: zero counters + split inputs/weights to bf16 hi/lo ----
    if (bid == 0 && tid < NE) g_cnt[tid] = 0;
    {
        uint2 hi, lo;
        for (long i = gtid; i < (long)TOK*HID/4; i += NT) {
            split4(((const float4*)x)[i], hi, lo);
            ((uint2*)g_xh)[i] = hi; ((uint2*)g_xl)[i] = lo;
        }
        for (long i = gtid; i < (long)NE*GUD*HID/4; i += NT) {
            split4(((const float4*)wgu)[i], hi, lo);
            ((uint2*)g_wuh)[i] = hi; ((uint2*)g_wul)[i] = lo;
        }
        for (long i = gtid; i < (long)NE*HID*IMD/4; i += NT) {
            split4(((const float4*)wd)[i], hi, lo);
            ((uint2*)g_wdh)[i] = hi; ((uint2*)g_wdl)[i] = lo;
        }
    }
    gbar(ls);

    // ---- P1: router (one warp per token) ----
    {
        int t = bid * 8 + wid;
        if (t < TOK) {
            const float* xr = x + (size_t)t * HID;
            float acc[NE];
#pragma unroll
            for (int e2 = 0; e2 < NE; e2++) acc[e2] = 0.f;
            for (int j = lane; j < HID; j += 32) {
                float xv = xr[j];
#pragma unroll
                for (int e2 = 0; e2 < NE; e2++) acc[e2] += xv * gw[e2*HID + j];
            }
#pragma unroll
            for (int e2 = 0; e2 < NE; e2++) acc[e2] = wsum(acc[e2]);
            if (lane == 0) {
                int i1 = 0; float v1 = acc[0];
#pragma unroll
                for (int e2 = 1; e2 < NE; e2++) if (acc[e2] > v1) { v1 = acc[e2]; i1 = e2; }
                int i2 = (i1 == 0) ? 1 : 0; float v2 = acc[i2];
#pragma unroll
                for (int e2 = 0; e2 < NE; e2++) if (e2 != i1 && acc[e2] > v2) { v2 = acc[e2]; i2 = e2; }
                float r  = expf(v2 - v1);          // full-E softmax + top-2 renorm
                float w1 = 1.f / (1.f + r);        // == 2-way softmax over {v1,v2}
                g_topw[2*t+0] = w1;
                g_topw[2*t+1] = r * w1;
                int p1 = atomicAdd(&g_cnt[i1], 1); g_list[i1*TOK + p1] = 2*t + 0;
                int p2 = atomicAdd(&g_cnt[i2], 1); g_list[i2*TOK + p2] = 2*t + 1;
            }
        }
    }
    gbar(ls);

    // ---- P2: GEMM1  x @ Wgu^T -> g_gu  (K=2048, N=1536) ----
    for (int job = bid; job < NE*8*12; job += NBLK) {
        int e  = job / 96;
        int mt = (job % 96) / 12;
        int nt = job % 12;
        int ne = g_cnt[e];
        if (mt * 128 >= ne) continue;
        mma_tile<HID, false>(g_xh, g_xl,
                             g_wuh + (size_t)e*GUD*HID, g_wul + (size_t)e*GUD*HID,
                             e, mt*128, nt*128, ne, sm, sb);
    }
    gbar(ls);

    // ---- P3: act h = silu(g)*u -> bf16 hi/lo ----
    {
        const int n4 = 2*TOK*IMD/4;
        for (int i = gtid; i < n4; i += NT) {
            int p  = i / (IMD/4);
            int j4 = i - p * (IMD/4);
            float4 g4 = *(const float4*)(g_gu + (size_t)p*GUD + 4*j4);
            float4 u4 = *(const float4*)(g_gu + (size_t)p*GUD + IMD + 4*j4);
            float4 h4;
            h4.x = (g4.x / (1.f + expf(-g4.x))) * u4.x;
            h4.y = (g4.y / (1.f + expf(-g4.y))) * u4.y;
            h4.z = (g4.z / (1.f + expf(-g4.z))) * u4.z;
            h4.w = (g4.w / (1.f + expf(-g4.w))) * u4.w;
            uint2 hi, lo;
            split4(h4, hi, lo);
            ((uint2*)g_hbh)[i] = hi; ((uint2*)g_hbl)[i] = lo;
        }
    }
    gbar(ls);

    // ---- P4: GEMM2  h @ Wd^T -> g_o2  (K=768, N=2048) ----
    for (int job = bid; job < NE*8*16; job += NBLK) {
        int e  = job / 128;
        int mt = (job % 128) / 16;
        int nt = job % 16;
        int ne = g_cnt[e];
        if (mt * 128 >= ne) continue;
        mma_tile<IMD, true>(g_hbh, g_hbl,
                            g_wdh + (size_t)e*HID*IMD, g_wdl + (size_t)e*HID*IMD,
                            e, mt*128, nt*128, ne, sm, sb);
    }
    gbar(ls);

    // ---- P5: combine out[t] = w1*y[2t] + w2*y[2t+1] ----
    {
        const int n4 = TOK*HID/4;
        for (int i = gtid; i < n4; i += NT) {
            int t  = i / (HID/4);
            int j4 = i - t * (HID/4);
            float w1 = g_topw[2*t+0], w2 = g_topw[2*t+1];
            float4 y1 = ((const float4*)g_o2)[(size_t)(2*t  )*(HID/4) + j4];
            float4 y2 = ((const float4*)g_o2)[(size_t)(2*t+1)*(HID/4) + j4];
            float4 o;
            o.x = w1*y1.x + w2*y2.x;
            o.y = w1*y1.y + w2*y2.y;
            o.z = w1*y1.z + w2*y2.z;
            o.w = w1*y1.w + w2*y2.w;
            ((float4*)out)[i] = o;
        }
    }
}

// ---------------- launch ----------------
extern "C" void kernel_launch(void* const* d_in, const int* in_sizes, int n_in,
                              void* d_out, int out_size) {
    const long EX = (long)TOK*HID, EG = (long)NE*HID;
    const long EU = (long)NE*GUD*HID, ED = (long)NE*HID*IMD;

    const float *x = nullptr, *gw = nullptr, *wgu = nullptr, *wd = nullptr;
    for (int i = 0; i < n_in; i++) {
        long sz = in_sizes[i];
        if      (sz == EX && !x)   x   = (const float*)d_in[i];
        else if (sz == EG && !gw)  gw  = (const float*)d_in[i];
        else if (sz == EU && !wgu) wgu = (const float*)d_in[i];
        else if (sz == ED && !wd)  wd  = (const float*)d_in[i];
    }
    if (!x || !gw || !wgu || !wd) {
        if (n_in < 4) return;
        x = (const float*)d_in[0]; gw = (const float*)d_in[1];
        wgu = (const float*)d_in[2]; wd = (const float*)d_in[3];
    }
    cudaFuncSetAttribute(k_moe, cudaFuncAttributeMaxDynamicSharedMemorySize, SMEM_BYTES);
    k_moe<<<NBLK, 256, SMEM_BYTES>>>(x, gw, wgu, wd, (float*)d_out);
}

// round 9
// speedup vs baseline: 6.1961x; 1.2118x over previous
#include <cuda_runtime.h>
#include <cuda_bf16.h>
#include <math.h>
#include <stdint.h>

#define TOK 1024
#define HID 2048
#define IMD 768
#define GUD 1536
#define NE  8
#define NBLK 148
#define NTH 512
#define NT (NBLK*NTH)

// ---- per-stage smem: 4 matrices of 128 rows x 64 bf16 (swizzled 128B rows) ----
#define SA_H 0
#define SA_L 16384
#define SB_H 32768
#define SB_L 49152
#define STAGE_BYTES 65536
#define NSTG 3
#define SMEM_BYTES (NSTG*STAGE_BYTES)

// ---------------- scratch (device globals) ----------------
__device__ __align__(16) int   g_cnt[NE];
__device__ __align__(16) int   g_list[NE*TOK];
__device__ __align__(16) float g_topw[2*TOK];
__device__ __align__(16) float g_gu[2*TOK*GUD];
__device__ __align__(16) float g_o2[2*TOK*HID];
__device__ __align__(16) __nv_bfloat16 g_xh [TOK*HID],     g_xl [TOK*HID];
__device__ __align__(16) __nv_bfloat16 g_wuh[NE*GUD*HID],  g_wul[NE*GUD*HID];
__device__ __align__(16) __nv_bfloat16 g_wdh[NE*HID*IMD],  g_wdl[NE*HID*IMD];
__device__ __align__(16) __nv_bfloat16 g_hbh[2*TOK*IMD],   g_hbl[2*TOK*IMD];
__device__ unsigned          g_bcnt   = 0;
__device__ volatile unsigned g_bsense = 0;

// ---------------- helpers ----------------
__device__ __forceinline__ uint32_t smem_u32(const void* p) {
    uint32_t a;
    asm("{ .reg .u64 t; cvta.to.shared.u64 t, %1; cvt.u32.u64 %0, t; }" : "=r"(a) : "l"(p));
    return a;
}
__device__ __forceinline__ void cp16(uint32_t dst, const void* src) {
    asm volatile("cp.async.cg.shared.global [%0], [%1], 16;" :: "r"(dst), "l"(src) : "memory");
}
__device__ __forceinline__ void cp16p(uint32_t dst, const void* src, int full) {
    asm volatile("cp.async.cg.shared.global [%0], [%1], 16, %2;"
                 :: "r"(dst), "l"(src), "r"(full ? 16 : 0) : "memory");
}
#define CP_COMMIT() asm volatile("cp.async.commit_group;" ::: "memory")
#define CP_WAIT(n)  asm volatile("cp.async.wait_group %0;" :: "n"(n) : "memory")

__device__ __forceinline__ void ldsm_x4(uint32_t r[4], uint32_t addr) {
    asm volatile("ldmatrix.sync.aligned.m8n8.x4.shared.b16 {%0,%1,%2,%3}, [%4];"
        : "=r"(r[0]), "=r"(r[1]), "=r"(r[2]), "=r"(r[3]) : "r"(addr));
}
__device__ __forceinline__ void mma_bf16(float c[4], const uint32_t a[4], const uint32_t b[2]) {
    asm volatile("mma.sync.aligned.m16n8k16.row.col.f32.bf16.bf16.f32 "
        "{%0,%1,%2,%3}, {%4,%5,%6,%7}, {%8,%9}, {%0,%1,%2,%3};"
        : "+f"(c[0]), "+f"(c[1]), "+f"(c[2]), "+f"(c[3])
        : "r"(a[0]), "r"(a[1]), "r"(a[2]), "r"(a[3]), "r"(b[0]), "r"(b[1]));
}
__device__ __forceinline__ void split4(float4 v, uint2& hi, uint2& lo) {
    __nv_bfloat16 h0 = __float2bfloat16(v.x), h1 = __float2bfloat16(v.y);
    __nv_bfloat16 h2 = __float2bfloat16(v.z), h3 = __float2bfloat16(v.w);
    __nv_bfloat16 l0 = __float2bfloat16(v.x - __bfloat162float(h0));
    __nv_bfloat16 l1 = __float2bfloat16(v.y - __bfloat162float(h1));
    __nv_bfloat16 l2 = __float2bfloat16(v.z - __bfloat162float(h2));
    __nv_bfloat16 l3 = __float2bfloat16(v.w - __bfloat162float(h3));
    hi.x = (uint32_t)__bfloat16_as_ushort(h0) | ((uint32_t)__bfloat16_as_ushort(h1) << 16);
    hi.y = (uint32_t)__bfloat16_as_ushort(h2) | ((uint32_t)__bfloat16_as_ushort(h3) << 16);
    lo.x = (uint32_t)__bfloat16_as_ushort(l0) | ((uint32_t)__bfloat16_as_ushort(l1) << 16);
    lo.y = (uint32_t)__bfloat16_as_ushort(l2) | ((uint32_t)__bfloat16_as_ushort(l3) << 16);
}
__device__ __forceinline__ void gbar(unsigned& ls) {
    __syncthreads();
    if (threadIdx.x == 0) {
        unsigned target = ls + 1u;
        __threadfence();
        unsigned old = atomicAdd(&g_bcnt, 1u);
        if (old == NBLK - 1u) { g_bcnt = 0u; __threadfence(); g_bsense = target; }
        else { while (g_bsense != target) __nanosleep(128); }
        __threadfence();
    }
    ls += 1u;
    __syncthreads();
}
__device__ __forceinline__ float wsum(float v) {
#pragma unroll
    for (int o = 16; o; o >>= 1) v += __shfl_xor_sync(0xffffffffu, v, o);
    return v;
}

// ---------------- 128x128xK warp-MMA tile, gathered A rows, 3-stage cp.async ----
template<int KD, bool SECOND>
__device__ __forceinline__ void mma_tile(
    const __nv_bfloat16* __restrict__ Ah, const __nv_bfloat16* __restrict__ Al,
    const __nv_bfloat16* __restrict__ Bh, const __nv_bfloat16* __restrict__ Bl,
    int e, int m0, int n0, int ne, char* sm, uint32_t sb)
{
    const int tid = threadIdx.x;
    const int wid = tid >> 5, lane = tid & 31;

    // ---- global->smem mapping: thread = (row, 2 chunks of 16B per matrix) ----
    const int lrow = tid >> 2;          // 0..127
    const int cq   = (tid & 3) * 2;     // 0,2,4,6 (chunks cq, cq+1 of 8)
    const int a_ok = (m0 + lrow < ne);
    const uint4 *agh, *agl;
    {
        int pair = a_ok ? g_list[e*TOK + m0 + lrow] : 0;
        size_t ar = (size_t)(SECOND ? pair : (pair >> 1)) * KD;
        agh = (const uint4*)(Ah + ar);
        agl = (const uint4*)(Al + ar);
    }
    const uint4* bgh = (const uint4*)(Bh + (size_t)(n0 + lrow) * KD);
    const uint4* bgl = (const uint4*)(Bl + (size_t)(n0 + lrow) * KD);

    uint32_t sts[2];
#pragma unroll
    for (int j = 0; j < 2; j++) {
        int ch = cq + j;
        sts[j] = (uint32_t)(lrow * 128 + ((ch ^ (lrow & 7)) << 4));
    }

    const int KBN = KD / 64;
    auto issue = [&](int kb, int stg) {
        uint32_t base = sb + (uint32_t)stg * STAGE_BYTES;
#pragma unroll
        for (int j = 0; j < 2; j++) {
            int ch = cq + j;
            cp16p(base + SA_H + sts[j], agh + kb*8 + ch, a_ok);
            cp16p(base + SA_L + sts[j], agl + kb*8 + ch, a_ok);
            cp16 (base + SB_H + sts[j], bgh + kb*8 + ch);
            cp16 (base + SB_L + sts[j], bgl + kb*8 + ch);
        }
        CP_COMMIT();
    };

    // ---- warp tile: 32m x 32n, warp grid 4x4 ----
    const int wm = (wid & 3) * 32;
    const int wn = (wid >> 2) * 32;
    const int q  = lane >> 3, r8 = lane & 7;
    const int a_m_base = wm + (q & 1) * 8 + r8;
    const int a_ch_off = (q >> 1);
    const int b_n_base = wn + (q >> 1) * 8 + r8;
    const int b_ch_off = (q & 1);

    float acc[2][4][4];
#pragma unroll
    for (int i = 0; i < 2; i++)
#pragma unroll
        for (int j = 0; j < 4; j++)
#pragma unroll
            for (int c = 0; c < 4; c++) acc[i][j][c] = 0.f;

    issue(0, 0);
    if (KBN > 1) issue(1, 1);

    for (int kb = 0; kb < KBN; kb++) {
        const int stg = kb % NSTG;
        if (kb == KBN - 1) { CP_WAIT(0); } else { CP_WAIT(1); }
        __syncthreads();                       // stage kb visible; all warps done kb-1
        if (kb + 2 < KBN) issue(kb + 2, (kb + 2) % NSTG);

        const uint32_t base = sb + (uint32_t)stg * STAGE_BYTES;
        const uint32_t saH = base + SA_H, saL = base + SA_L;
        const uint32_t sbH = base + SB_H, sbL = base + SB_L;

#pragma unroll
        for (int ks = 0; ks < 4; ks++) {
            uint32_t ahf[2][4], alf[2][4];
#pragma unroll
            for (int mi = 0; mi < 2; mi++) {
                int m_ld = a_m_base + mi * 16;
                uint32_t off = (uint32_t)(m_ld * 128 + (((ks*2 + a_ch_off) ^ (m_ld & 7)) << 4));
                ldsm_x4(ahf[mi], saH + off);
                ldsm_x4(alf[mi], saL + off);
            }
#pragma unroll
            for (int nb = 0; nb < 2; nb++) {
                int n_ld = b_n_base + nb * 16;
                uint32_t off = (uint32_t)(n_ld * 128 + (((ks*2 + b_ch_off) ^ (n_ld & 7)) << 4));
                uint32_t bhf[4], blf[4];
                ldsm_x4(bhf, sbH + off);
                ldsm_x4(blf, sbL + off);
#pragma unroll
                for (int mi = 0; mi < 2; mi++) {
#pragma unroll
                    for (int h = 0; h < 2; h++) {
                        float* c = acc[mi][nb*2 + h];
                        mma_bf16(c, ahf[mi], &bhf[2*h]);
                        mma_bf16(c, ahf[mi], &blf[2*h]);
                        mma_bf16(c, alf[mi], &bhf[2*h]);
                    }
                }
            }
        }
    }

    // ---- epilogue ----
    const int g  = lane >> 2, t4 = lane & 3;
#pragma unroll
    for (int mi = 0; mi < 2; mi++) {
        int mr0 = m0 + wm + mi*16 + g;
        int mr1 = mr0 + 8;
        float* row0 = nullptr; float* row1 = nullptr;
        if (mr0 < ne) {
            int p = g_list[e*TOK + mr0];
            row0 = SECOND ? (g_o2 + (size_t)p * HID) : (g_gu + (size_t)p * GUD);
        }
        if (mr1 < ne) {
            int p = g_list[e*TOK + mr1];
            row1 = SECOND ? (g_o2 + (size_t)p * HID) : (g_gu + (size_t)p * GUD);
        }
#pragma unroll
        for (int nj = 0; nj < 4; nj++) {
            int n = n0 + wn + nj*8 + t4*2;
            if (row0) *(float2*)(row0 + n) = make_float2(acc[mi][nj][0], acc[mi][nj][1]);
            if (row1) *(float2*)(row1 + n) = make_float2(acc[mi][nj][2], acc[mi][nj][3]);
        }
    }
    __syncthreads();   // stages safe for next tile's issue
}

// ---------------- persistent fused MoE kernel ----------------
__global__ void __launch_bounds__(NTH) k_moe(
    const float* __restrict__ x,   const float* __restrict__ gw,
    const float* __restrict__ wgu, const float* __restrict__ wd,
    float* __restrict__ out)
{
    extern __shared__ char sm[];
    const uint32_t sb = smem_u32(sm);
    const int tid  = threadIdx.x;
    const int wid  = tid >> 5;
    const int lane = tid & 31;
    const int bid  = blockIdx.x;
    const int gtid = bid * NTH + tid;
    unsigned ls = g_bsense;

    // ---- P0: zero counters + split inputs/weights to bf16 hi/lo ----
    if (bid == 0 && tid < NE) g_cnt[tid] = 0;
    {
        uint2 hi, lo;
        for (long i = gtid; i < (long)TOK*HID/4; i += NT) {
            split4(((const float4*)x)[i], hi, lo);
            ((uint2*)g_xh)[i] = hi; ((uint2*)g_xl)[i] = lo;
        }
        for (long i = gtid; i < (long)NE*GUD*HID/4; i += NT) {
            split4(((const float4*)wgu)[i], hi, lo);
            ((uint2*)g_wuh)[i] = hi; ((uint2*)g_wul)[i] = lo;
        }
        for (long i = gtid; i < (long)NE*HID*IMD/4; i += NT) {
            split4(((const float4*)wd)[i], hi, lo);
            ((uint2*)g_wdh)[i] = hi; ((uint2*)g_wdl)[i] = lo;
        }
    }
    gbar(ls);

    // ---- P1: router (one warp per token) ----
    {
        int t = bid * 16 + wid;
        if (t < TOK) {
            const float* xr = x + (size_t)t * HID;
            float acc[NE];
#pragma unroll
            for (int e2 = 0; e2 < NE; e2++) acc[e2] = 0.f;
            for (int j = lane; j < HID; j += 32) {
                float xv = xr[j];
#pragma unroll
                for (int e2 = 0; e2 < NE; e2++) acc[e2] += xv * gw[e2*HID + j];
            }
#pragma unroll
            for (int e2 = 0; e2 < NE; e2++) acc[e2] = wsum(acc[e2]);
            if (lane == 0) {
                int i1 = 0; float v1 = acc[0];
#pragma unroll
                for (int e2 = 1; e2 < NE; e2++) if (acc[e2] > v1) { v1 = acc[e2]; i1 = e2; }
                int i2 = (i1 == 0) ? 1 : 0; float v2 = acc[i2];
#pragma unroll
                for (int e2 = 0; e2 < NE; e2++) if (e2 != i1 && acc[e2] > v2) { v2 = acc[e2]; i2 = e2; }
                float r  = expf(v2 - v1);          // full-E softmax + top-2 renorm
                float w1 = 1.f / (1.f + r);        // == 2-way softmax over {v1,v2}
                g_topw[2*t+0] = w1;
                g_topw[2*t+1] = r * w1;
                int p1 = atomicAdd(&g_cnt[i1], 1); g_list[i1*TOK + p1] = 2*t + 0;
                int p2 = atomicAdd(&g_cnt[i2], 1); g_list[i2*TOK + p2] = 2*t + 1;
            }
        }
    }
    gbar(ls);

    // ---- P2: GEMM1  x @ Wgu^T -> g_gu  (K=2048, N=1536) ----
    for (int job = bid; job < NE*8*12; job += NBLK) {
        int e  = job / 96;
        int mt = (job % 96) / 12;
        int nt = job % 12;
        int ne = g_cnt[e];
        if (mt * 128 >= ne) continue;
        mma_tile<HID, false>(g_xh, g_xl,
                             g_wuh + (size_t)e*GUD*HID, g_wul + (size_t)e*GUD*HID,
                             e, mt*128, nt*128, ne, sm, sb);
    }
    gbar(ls);

    // ---- P3: act h = silu(g)*u -> bf16 hi/lo ----
    {
        const int n4 = 2*TOK*IMD/4;
        for (int i = gtid; i < n4; i += NT) {
            int p  = i / (IMD/4);
            int j4 = i - p * (IMD/4);
            float4 g4 = *(const float4*)(g_gu + (size_t)p*GUD + 4*j4);
            float4 u4 = *(const float4*)(g_gu + (size_t)p*GUD + IMD + 4*j4);
            float4 h4;
            h4.x = (g4.x / (1.f + expf(-g4.x))) * u4.x;
            h4.y = (g4.y / (1.f + expf(-g4.y))) * u4.y;
            h4.z = (g4.z / (1.f + expf(-g4.z))) * u4.z;
            h4.w = (g4.w / (1.f + expf(-g4.w))) * u4.w;
            uint2 hi, lo;
            split4(h4, hi, lo);
            ((uint2*)g_hbh)[i] = hi; ((uint2*)g_hbl)[i] = lo;
        }
    }
    gbar(ls);

    // ---- P4: GEMM2  h @ Wd^T -> g_o2  (K=768, N=2048) ----
    for (int job = bid; job < NE*8*16; job += NBLK) {
        int e  = job / 128;
        int mt = (job % 128) / 16;
        int nt = job % 16;
        int ne = g_cnt[e];
        if (mt * 128 >= ne) continue;
        mma_tile<IMD, true>(g_hbh, g_hbl,
                            g_wdh + (size_t)e*HID*IMD, g_wdl + (size_t)e*HID*IMD,
                            e, mt*128, nt*128, ne, sm, sb);
    }
    gbar(ls);

    // ---- P5: combine out[t] = w1*y[2t] + w2*y[2t+1] ----
    {
        const int n4 = TOK*HID/4;
        for (int i = gtid; i < n4; i += NT) {
            int t  = i / (HID/4);
            int j4 = i - t * (HID/4);
            float w1 = g_topw[2*t+0], w2 = g_topw[2*t+1];
            float4 y1 = ((const float4*)g_o2)[(size_t)(2*t  )*(HID/4) + j4];
            float4 y2 = ((const float4*)g_o2)[(size_t)(2*t+1)*(HID/4) + j4];
            float4 o;
            o.x = w1*y1.x + w2*y2.x;
            o.y = w1*y1.y + w2*y2.y;
            o.z = w1*y1.z + w2*y2.z;
            o.w = w1*y1.w + w2*y2.w;
            ((float4*)out)[i] = o;
        }
    }
}

// ---------------- launch ----------------
extern "C" void kernel_launch(void* const* d_in, const int* in_sizes, int n_in,
                              void* d_out, int out_size) {
    const long EX = (long)TOK*HID, EG = (long)NE*HID;
    const long EU = (long)NE*GUD*HID, ED = (long)NE*HID*IMD;

    const float *x = nullptr, *gw = nullptr, *wgu = nullptr, *wd = nullptr;
    for (int i = 0; i < n_in; i++) {
        long sz = in_sizes[i];
        if      (sz == EX && !x)   x   = (const float*)d_in[i];
        else if (sz == EG && !gw)  gw  = (const float*)d_in[i];
        else if (sz == EU && !wgu) wgu = (const float*)d_in[i];
        else if (sz == ED && !wd)  wd  = (const float*)d_in[i];
    }
    if (!x || !gw || !wgu || !wd) {
        if (n_in < 4) return;
        x = (const float*)d_in[0]; gw = (const float*)d_in[1];
        wgu = (const float*)d_in[2]; wd = (const float*)d_in[3];
    }
    cudaFuncSetAttribute(k_moe, cudaFuncAttributeMaxDynamicSharedMemorySize, SMEM_BYTES);
    k_moe<<<NBLK, NTH, SMEM_BYTES>>>(x, gw, wgu, wd, (float*)d_out);
}